// round 3
// baseline (speedup 1.0000x reference)
#include <cuda_runtime.h>

#define D    64
#define G3   192
#define NPAD 50176
#define EMAXSZ 800000
#define SAS  34   // transposed tile stride (even -> 8B-aligned pairs)

typedef unsigned long long ULL;

#define FMA2(d, a, b, c) asm("fma.rn.f32x2 %0, %1, %2, %3;" : "=l"(d) : "l"(a), "l"(b), "l"(c))
#define PACK2(d, lo, hi) asm("mov.b64 %0, {%1, %2};" : "=l"(d) : "f"(lo), "f"(hi))
#define UNPACK2(lo, hi, s) asm("mov.b64 {%0, %1}, %2;" : "=f"(lo), "=f"(hi) : "l"(s))

// ---------------- device scratch ----------------
__device__ __align__(16) float g_h [NPAD * D];
__device__ __align__(16) float g_h2[NPAD * D];
__device__ __align__(16) float g_ah[NPAD * D];
__device__ __align__(16) float g_C [3 * D * G3];   // C_i = W_i @ W_ih^T
__device__ __align__(16) float g_W [D * G3];       // W_hh transposed [k][g]
__device__ int g_deg[NPAD];
__device__ int g_off[NPAD + 1];
__device__ int g_cur[NPAD];
__device__ int g_ssrc[EMAXSZ];

// ---------------- node transform: h = relu(x @ Wnt^T + bnt) ----------------
__global__ void k_nt(const float* __restrict__ x, const float* __restrict__ Wnt,
                     const float* __restrict__ bnt, int n) {
    int idx = blockIdx.x * blockDim.x + threadIdx.x;
    if (idx >= n * D) return;
    int node = idx >> 6, d = idx & 63;
    float acc = bnt[d];
    const float* xr = x + node * 6;
    const float* wr = Wnt + d * 6;
#pragma unroll
    for (int k = 0; k < 6; k++) acc = fmaf(xr[k], wr[k], acc);
    g_h[idx] = fmaxf(acc, 0.f);
}

// ---------------- precompute C_i[k][g] = sum_j weight[i][k][j] * W_ih[g][j] ----------------
__global__ void k_makeC(const float* __restrict__ wt, const float* __restrict__ Wih) {
    int idx = blockIdx.x * blockDim.x + threadIdx.x;
    if (idx >= 3 * D * G3) return;
    int g = idx % G3;
    int k = (idx / G3) & 63;
    int i = idx / (D * G3);
    const float* wr = wt + i * D * D + k * D;
    const float* ir = Wih + g * D;
    float s = 0.f;
#pragma unroll 8
    for (int j = 0; j < D; j++) s = fmaf(wr[j], ir[j], s);
    g_C[idx] = s;
}

// ---------------- transpose W_hh into [k][g] ----------------
__global__ void k_transW(const float* __restrict__ Whh) {
    int idx = blockIdx.x * blockDim.x + threadIdx.x;
    if (idx >= D * G3) return;
    int g = idx % G3, k = idx / G3;
    g_W[idx] = Whh[g * D + k];
}

// ---------------- CSR build ----------------
__global__ void k_zero(int n) {
    int i = blockIdx.x * blockDim.x + threadIdx.x;
    if (i < n) g_deg[i] = 0;
}

__global__ void k_hist(const int* __restrict__ ei, int e, int n) {
    int i = blockIdx.x * blockDim.x + threadIdx.x;
    if (i < e) {
        int d = ei[e + i];
        if ((unsigned)d < (unsigned)n) atomicAdd(&g_deg[d], 1);
    }
}

__global__ void k_scan(int n, int e) {
    __shared__ int part[1024];
    int t = threadIdx.x;
    int ch = (n + 1023) >> 10;
    int lo = t * ch, hi = lo + ch; if (hi > n) hi = n;
    int s = 0;
    for (int i = lo; i < hi; i++) s += g_deg[i];
    part[t] = s;
    __syncthreads();
    for (int ofs = 1; ofs < 1024; ofs <<= 1) {
        int v = (t >= ofs) ? part[t - ofs] : 0;
        __syncthreads();
        part[t] += v;
        __syncthreads();
    }
    int run = part[t] - s;
    for (int i = lo; i < hi; i++) {
        int d = g_deg[i];
        g_off[i] = run;
        g_cur[i] = run;
        run += d;
    }
    if (t == 0) g_off[n] = e;
}

__global__ void k_scatter(const int* __restrict__ ei, int e, int n) {
    int i = blockIdx.x * blockDim.x + threadIdx.x;
    if (i < e) {
        int dnode = ei[e + i];
        int snode = ei[i];
        if ((unsigned)dnode < (unsigned)n && (unsigned)snode < (unsigned)n) {
            int pos = atomicAdd(&g_cur[dnode], 1);
            g_ssrc[pos] = snode;
        }
    }
}

// ---------------- pull aggregate: float4 lanes, 2 edges per warp step ----------------
__global__ void k_agg(int hb, int n) {
    const float* __restrict__ hin = hb ? g_h2 : g_h;
    int w = (blockIdx.x * blockDim.x + threadIdx.x) >> 5;
    int lane = threadIdx.x & 31;
    if (w >= n) return;
    int sub = lane >> 4, l16 = lane & 15;
    int beg = g_off[w], end = g_off[w + 1];
    const float4* h4 = (const float4*)hin;
    float ax = 0.f, ay = 0.f, az = 0.f, aw = 0.f;
    for (int e0 = beg; e0 < end; e0 += 32) {
        int m = end - e0; if (m > 32) m = 32;
        int s = (lane < m) ? g_ssrc[e0 + lane] : 0;
#pragma unroll 4
        for (int j = 0; j < m; j += 2) {
            int jj = j + sub;
            int sj = __shfl_sync(0xffffffffu, s, jj & 31);
            if (jj < m) {
                float4 v = __ldg(&h4[sj * 16 + l16]);
                ax += v.x; ay += v.y; az += v.z; aw += v.w;
            }
        }
    }
    ax += __shfl_down_sync(0xffffffffu, ax, 16);
    ay += __shfl_down_sync(0xffffffffu, ay, 16);
    az += __shfl_down_sync(0xffffffffu, az, 16);
    aw += __shfl_down_sync(0xffffffffu, aw, 16);
    if (sub == 0) {
        float4 o; o.x = ax; o.y = ay; o.z = az; o.w = aw;
        ((float4*)g_ah)[w * 16 + l16] = o;
    }
}

// ---------------- fused GRU with packed f32x2 FMAs ----------------
// 256 threads, 32 nodes/block. Thread (c = tid&63, ng = tid>>6) owns gate
// columns {c, c+64, c+128} for 4 node-PAIRS -> 24 ULL (48 fp32) accumulators.
__global__ __launch_bounds__(256)
void k_gru(int hb, int layer, float* __restrict__ outp,
           const float* __restrict__ bi, const float* __restrict__ bh, int n) {
    const float* __restrict__ hin  = hb ? g_h2 : g_h;
    float* __restrict__ hout = outp ? outp : (hb ? g_h : g_h2);
    const float* __restrict__ Cmat = g_C + layer * D * G3;

    __shared__ float sCp[16 * 128];          // gates (0,1) interleaved: [k2][c][2]
    __shared__ float sC2[16 * 64];           // gate 2:                  [k2][c]
    __shared__ float sWp[16 * 128];
    __shared__ float sW2[16 * 64];
    __shared__ __align__(16) float sAt[D * SAS];  // A transposed [k][node]
    __shared__ __align__(16) float sHt[D * SAS];  // H transposed [k][node]

    int tid = threadIdx.x;
    int node0 = blockIdx.x << 5;
    {
        const float4* A4 = (const float4*)(g_ah + node0 * D);
        const float4* H4 = (const float4*)(hin + node0 * D);
#pragma unroll
        for (int i = 0; i < 2; i++) {
            int f4 = tid + (i << 8);         // 0..511
            int node = f4 >> 4, kb = (f4 & 15) << 2;
            float4 va = A4[f4];
            float4 vh = H4[f4];
            sAt[(kb + 0) * SAS + node] = va.x;
            sAt[(kb + 1) * SAS + node] = va.y;
            sAt[(kb + 2) * SAS + node] = va.z;
            sAt[(kb + 3) * SAS + node] = va.w;
            sHt[(kb + 0) * SAS + node] = vh.x;
            sHt[(kb + 1) * SAS + node] = vh.y;
            sHt[(kb + 2) * SAS + node] = vh.z;
            sHt[(kb + 3) * SAS + node] = vh.w;
        }
    }

    int c = tid & 63, ng = tid >> 6;
    ULL pa0[4], pa1[4], pa2[4], ph0[4], ph1[4], ph2[4];
#pragma unroll
    for (int jp = 0; jp < 4; jp++) { pa0[jp]=pa1[jp]=pa2[jp]=ph0[jp]=ph1[jp]=ph2[jp]=0ull; }

    for (int kc = 0; kc < 4; kc++) {
        __syncthreads();
        // stage 16-k weight chunk, gate-pair interleaved
        for (int idx = tid; idx < 16 * G3; idx += 256) {
            int k2 = idx / G3, g = idx - k2 * G3;
            float vc = Cmat[(kc * 16 + k2) * G3 + g];
            float vw = g_W [(kc * 16 + k2) * G3 + g];
            if (g < 128) {
                int cc = g & 63, gt = g >> 6;
                sCp[k2 * 128 + cc * 2 + gt] = vc;
                sWp[k2 * 128 + cc * 2 + gt] = vw;
            } else {
                sC2[k2 * 64 + g - 128] = vc;
                sW2[k2 * 64 + g - 128] = vw;
            }
        }
        __syncthreads();
#pragma unroll
        for (int k2 = 0; k2 < 16; k2++) {
            float2 cb = *(const float2*)(sCp + k2 * 128 + c * 2);
            float  c2 = sC2[k2 * 64 + c];
            float2 wb = *(const float2*)(sWp + k2 * 128 + c * 2);
            float  w2 = sW2[k2 * 64 + c];
            ULL B0, B1, B2, W0, W1, W2;
            PACK2(B0, cb.x, cb.x); PACK2(B1, cb.y, cb.y); PACK2(B2, c2, c2);
            PACK2(W0, wb.x, wb.x); PACK2(W1, wb.y, wb.y); PACK2(W2, w2, w2);
            int k = (kc << 4) + k2;
            const ULL* Ak = (const ULL*)(sAt + k * SAS + (ng << 3));
            const ULL* Hk = (const ULL*)(sHt + k * SAS + (ng << 3));
#pragma unroll
            for (int jp = 0; jp < 4; jp++) {
                ULL av = Ak[jp];
                ULL hv = Hk[jp];
                FMA2(pa0[jp], av, B0, pa0[jp]);
                FMA2(pa1[jp], av, B1, pa1[jp]);
                FMA2(pa2[jp], av, B2, pa2[jp]);
                FMA2(ph0[jp], hv, W0, ph0[jp]);
                FMA2(ph1[jp], hv, W1, ph1[jp]);
                FMA2(ph2[jp], hv, W2, ph2[jp]);
            }
        }
    }

    float bi0 = bi[c], bi1 = bi[c + 64], bi2 = bi[c + 128];
    float bh0 = bh[c], bh1 = bh[c + 64], bh2 = bh[c + 128];
#pragma unroll
    for (int jp = 0; jp < 4; jp++) {
        float a0x, a0y, a1x, a1y, a2x, a2y, h0x, h0y, h1x, h1y, h2x, h2y;
        UNPACK2(a0x, a0y, pa0[jp]); UNPACK2(a1x, a1y, pa1[jp]); UNPACK2(a2x, a2y, pa2[jp]);
        UNPACK2(h0x, h0y, ph0[jp]); UNPACK2(h1x, h1y, ph1[jp]); UNPACK2(h2x, h2y, ph2[jp]);
#pragma unroll
        for (int t = 0; t < 2; t++) {
            int nl = (ng << 3) + (jp << 1) + t;
            int node = node0 + nl;
            if (node < n) {
                float ai0 = t ? a0y : a0x, ai1 = t ? a1y : a1x, ai2 = t ? a2y : a2x;
                float ah0 = t ? h0y : h0x, ah1 = t ? h1y : h1x, ah2 = t ? h2y : h2x;
                float xr = ai0 + bi0 + ah0 + bh0;
                float xz = ai1 + bi1 + ah1 + bh1;
                float r = 1.f / (1.f + __expf(-xr));
                float z = 1.f / (1.f + __expf(-xz));
                float nn = tanhf(fmaf(r, ah2 + bh2, ai2 + bi2));
                float hp = sHt[c * SAS + nl];
                hout[node * D + c] = (1.f - z) * nn + z * hp;
            }
        }
    }
}

// ---------------- launch ----------------
extern "C" void kernel_launch(void* const* d_in, const int* in_sizes, int n_in,
                              void* d_out, int out_size) {
    const float* x   = (const float*)d_in[0];
    const int*   ei  = (const int*)d_in[1];      // int32: src[0..e), dst[e..2e)
    const float* Wnt = (const float*)d_in[4];
    const float* bnt = (const float*)d_in[5];
    const float* wt  = (const float*)d_in[6];
    const float* Wih = (const float*)d_in[7];
    const float* Whh = (const float*)d_in[8];
    const float* bi  = (const float*)d_in[9];
    const float* bh  = (const float*)d_in[10];
    float* out = (float*)d_out;

    int n = in_sizes[0] / 6;   // 50000
    int e = in_sizes[1] / 2;   // 800000

    k_nt     <<<(n * D + 255) / 256, 256>>>(x, Wnt, bnt, n);
    k_makeC  <<<(3 * D * G3 + 255) / 256, 256>>>(wt, Wih);
    k_transW <<<(D * G3 + 255) / 256, 256>>>(Whh);
    k_zero   <<<(n + 255) / 256, 256>>>(n);
    k_hist   <<<(e + 255) / 256, 256>>>(ei, e, n);
    k_scan   <<<1, 1024>>>(n, e);
    k_scatter<<<(e + 255) / 256, 256>>>(ei, e, n);

    int aggGrid = (n + 7) / 8;      // one warp per node
    int gruGrid = (n + 31) / 32;    // 32 nodes per block

    k_agg<<<aggGrid, 256>>>(0, n);
    k_gru<<<gruGrid, 256>>>(0, 0, nullptr, bi, bh, n);
    k_agg<<<aggGrid, 256>>>(1, n);
    k_gru<<<gruGrid, 256>>>(1, 1, nullptr, bi, bh, n);
    k_agg<<<aggGrid, 256>>>(0, n);
    k_gru<<<gruGrid, 256>>>(0, 2, out, bi, bh, n);
}

// round 4
// speedup vs baseline: 1.3421x; 1.3421x over previous
#include <cuda_runtime.h>

#define D   64
#define G3  192
#define NPAD 50176          // 196 * 256
#define NBLK 196
#define EMAXSZ 800000

// ---------------- device scratch (no allocations allowed) ----------------
__device__ __align__(16) float g_h [NPAD * D];
__device__ __align__(16) float g_h2[NPAD * D];
__device__ __align__(16) float g_ah[NPAD * D];
__device__ __align__(16) float g_C [3 * D * G3];   // C_i = W_i @ W_ih^T
__device__ __align__(16) float g_W [D * G3];       // W_hh transposed [k][g]
__device__ int g_deg[NPAD];
__device__ int g_incl[NPAD];
__device__ int g_bsum[NBLK];
__device__ int g_boff[NBLK];
__device__ int g_off[NPAD + 1];
__device__ int g_cur[NPAD];
__device__ int g_ssrc[EMAXSZ];

// ---------------- node transform: h = relu(x @ Wnt^T + bnt) ----------------
__global__ void k_nt(const float* __restrict__ x, const float* __restrict__ Wnt,
                     const float* __restrict__ bnt, int n) {
    int idx = blockIdx.x * blockDim.x + threadIdx.x;
    if (idx >= n * D) return;
    int node = idx >> 6, d = idx & 63;
    float acc = bnt[d];
    const float* xr = x + node * 6;
    const float* wr = Wnt + d * 6;
#pragma unroll
    for (int k = 0; k < 6; k++) acc = fmaf(xr[k], wr[k], acc);
    g_h[idx] = fmaxf(acc, 0.f);
}

// ---------------- precompute C_i[k][g] = sum_j weight[i][k][j] * W_ih[g][j] ----------------
__global__ void k_makeC(const float* __restrict__ wt, const float* __restrict__ Wih) {
    int idx = blockIdx.x * blockDim.x + threadIdx.x;
    if (idx >= 3 * D * G3) return;
    int g = idx % G3;
    int k = (idx / G3) & 63;
    int i = idx / (D * G3);
    const float* wr = wt + i * D * D + k * D;
    const float* ir = Wih + g * D;
    float s = 0.f;
#pragma unroll 8
    for (int j = 0; j < D; j++) s = fmaf(wr[j], ir[j], s);
    g_C[idx] = s;
}

// ---------------- transpose W_hh into [k][g] ----------------
__global__ void k_transW(const float* __restrict__ Whh) {
    int idx = blockIdx.x * blockDim.x + threadIdx.x;
    if (idx >= D * G3) return;
    int g = idx % G3, k = idx / G3;
    g_W[idx] = Whh[g * D + k];
}

// ---------------- CSR build: histogram / parallel scan / scatter ----------------
__global__ void k_zero() {
    int i = blockIdx.x * blockDim.x + threadIdx.x;
    if (i < NPAD) g_deg[i] = 0;
}

// edge_index is int32 (JAX x64 disabled): src = ei[0..e), dst = ei[e..2e)
__global__ void k_hist(const int* __restrict__ ei, int e, int n) {
    int i = blockIdx.x * blockDim.x + threadIdx.x;
    if (i < e) {
        int d = ei[e + i];
        if ((unsigned)d < (unsigned)n) atomicAdd(&g_deg[d], 1);
    }
}

// per-block inclusive scan of 256-element chunks
__global__ __launch_bounds__(256) void k_scanA() {
    __shared__ int sh[256];
    int t = threadIdx.x;
    int i = blockIdx.x * 256 + t;
    int v = g_deg[i];
    sh[t] = v;
    __syncthreads();
#pragma unroll
    for (int ofs = 1; ofs < 256; ofs <<= 1) {
        int u = (t >= ofs) ? sh[t - ofs] : 0;
        __syncthreads();
        sh[t] += u;
        __syncthreads();
    }
    g_incl[i] = sh[t];
    if (t == 255) g_bsum[blockIdx.x] = sh[255];
}

// single-block exclusive scan of the 196 block sums
__global__ __launch_bounds__(256) void k_scanB() {
    __shared__ int sh[256];
    int t = threadIdx.x;
    int v = (t < NBLK) ? g_bsum[t] : 0;
    sh[t] = v;
    __syncthreads();
#pragma unroll
    for (int ofs = 1; ofs < 256; ofs <<= 1) {
        int u = (t >= ofs) ? sh[t - ofs] : 0;
        __syncthreads();
        sh[t] += u;
        __syncthreads();
    }
    if (t < NBLK) g_boff[t] = sh[t] - v;   // exclusive
}

// write exclusive offsets + running cursors
__global__ __launch_bounds__(256) void k_scanC(int e) {
    int i = blockIdx.x * 256 + threadIdx.x;
    int off = g_boff[blockIdx.x] + g_incl[i] - g_deg[i];
    g_off[i] = off;
    g_cur[i] = off;
    if (i == 0) g_off[NPAD] = e;
}

__global__ void k_scatter(const int* __restrict__ ei, int e, int n) {
    int i = blockIdx.x * blockDim.x + threadIdx.x;
    if (i < e) {
        int dnode = ei[e + i];
        int snode = ei[i];
        if ((unsigned)dnode < (unsigned)n && (unsigned)snode < (unsigned)n) {
            int pos = atomicAdd(&g_cur[dnode], 1);
            g_ssrc[pos] = snode;
        }
    }
}

// ---------------- pull-based aggregate: ah[v] = sum_{e in CSR[v]} h[src[e]] ----------------
__global__ void k_agg(int hb, int n) {
    const float* __restrict__ hin = hb ? g_h2 : g_h;
    int w = (blockIdx.x * blockDim.x + threadIdx.x) >> 5;
    int lane = threadIdx.x & 31;
    if (w >= n) return;
    int beg = g_off[w], end = g_off[w + 1];
    const float2* h2 = (const float2*)hin;
    float ax = 0.f, ay = 0.f;
    for (int e0 = beg; e0 < end; e0 += 32) {
        int m = end - e0; if (m > 32) m = 32;
        int s = (lane < m) ? g_ssrc[e0 + lane] : 0;
#pragma unroll 4
        for (int j = 0; j < m; j++) {
            int sj = __shfl_sync(0xffffffffu, s, j);
            float2 v = __ldg(&h2[sj * 32 + lane]);
            ax += v.x; ay += v.y;
        }
    }
    float2 o; o.x = ax; o.y = ay;
    ((float2*)g_ah)[w * 32 + lane] = o;
}

// ---------------- fused GRU: gi = ah@C_i + b_ih ; gh = h@W_hh^T + b_hh ; gates ----------------
// Block: 256 threads, 32 nodes. Thread (c = tid&63, ng = tid>>6) owns
// gate-triplet columns {c, c+64, c+128} for 8 nodes -> 48 accumulators.
__global__ __launch_bounds__(256)
void k_gru(int hb, int layer, float* __restrict__ outp,
           const float* __restrict__ bi, const float* __restrict__ bh, int n) {
    const float* __restrict__ hin  = hb ? g_h2 : g_h;
    float* __restrict__ hout = outp ? outp : (hb ? g_h : g_h2);
    const float* __restrict__ Cmat = g_C + layer * D * G3;

    __shared__ float sC[16 * G3];   // 12 KB: 16-k chunk of C_i
    __shared__ float sW[16 * G3];   // 12 KB: 16-k chunk of W_hh^T
    __shared__ float sA[32 * D];    //  8 KB: ah tile
    __shared__ float sH[32 * D];    //  8 KB: h tile

    int tid = threadIdx.x;
    int node0 = blockIdx.x << 5;
    {
        const float4* A4 = (const float4*)(g_ah + node0 * D);
        const float4* H4 = (const float4*)(hin + node0 * D);
#pragma unroll
        for (int i = 0; i < 2; i++) {
            ((float4*)sA)[tid + (i << 8)] = A4[tid + (i << 8)];
            ((float4*)sH)[tid + (i << 8)] = H4[tid + (i << 8)];
        }
    }
    int c = tid & 63, ng = tid >> 6;
    float ai0[8], ai1[8], ai2[8], ah0[8], ah1[8], ah2[8];
#pragma unroll
    for (int j = 0; j < 8; j++) { ai0[j]=ai1[j]=ai2[j]=ah0[j]=ah1[j]=ah2[j]=0.f; }

    const float* Ab = sA + ng * 8 * D;
    const float* Hb = sH + ng * 8 * D;

    for (int kc = 0; kc < 4; kc++) {
        if (kc) __syncthreads();
        const float4* C4 = (const float4*)(Cmat + kc * 16 * G3);
        const float4* W4 = (const float4*)(g_W  + kc * 16 * G3);
#pragma unroll
        for (int i = 0; i < 3; i++) {
            ((float4*)sC)[tid + (i << 8)] = C4[tid + (i << 8)];
            ((float4*)sW)[tid + (i << 8)] = W4[tid + (i << 8)];
        }
        __syncthreads();
#pragma unroll 4
        for (int k2 = 0; k2 < 16; k2++) {
            int k = (kc << 4) + k2;
            float b0 = sC[k2 * G3 + c];
            float b1 = sC[k2 * G3 + 64 + c];
            float b2 = sC[k2 * G3 + 128 + c];
            float w0 = sW[k2 * G3 + c];
            float w1 = sW[k2 * G3 + 64 + c];
            float w2 = sW[k2 * G3 + 128 + c];
#pragma unroll
            for (int j = 0; j < 8; j++) {
                float av = Ab[j * D + k];
                float hv = Hb[j * D + k];
                ai0[j] = fmaf(av, b0, ai0[j]);
                ai1[j] = fmaf(av, b1, ai1[j]);
                ai2[j] = fmaf(av, b2, ai2[j]);
                ah0[j] = fmaf(hv, w0, ah0[j]);
                ah1[j] = fmaf(hv, w1, ah1[j]);
                ah2[j] = fmaf(hv, w2, ah2[j]);
            }
        }
    }

    float bi0 = bi[c], bi1 = bi[c + 64], bi2 = bi[c + 128];
    float bh0 = bh[c], bh1 = bh[c + 64], bh2 = bh[c + 128];
#pragma unroll
    for (int j = 0; j < 8; j++) {
        int node = node0 + ng * 8 + j;
        if (node < n) {
            float xr = ai0[j] + bi0 + ah0[j] + bh0;
            float xz = ai1[j] + bi1 + ah1[j] + bh1;
            float r = 1.f / (1.f + __expf(-xr));
            float z = 1.f / (1.f + __expf(-xz));
            float nn = tanhf(fmaf(r, ah2[j] + bh2, ai2[j] + bi2));
            float hp = sH[(ng * 8 + j) * D + c];
            hout[node * D + c] = (1.f - z) * nn + z * hp;
        }
    }
}

// ---------------- launch ----------------
extern "C" void kernel_launch(void* const* d_in, const int* in_sizes, int n_in,
                              void* d_out, int out_size) {
    const float* x   = (const float*)d_in[0];
    const int*   ei  = (const int*)d_in[1];      // int32: src[0..e), dst[e..2e)
    const float* Wnt = (const float*)d_in[4];
    const float* bnt = (const float*)d_in[5];
    const float* wt  = (const float*)d_in[6];
    const float* Wih = (const float*)d_in[7];
    const float* Whh = (const float*)d_in[8];
    const float* bi  = (const float*)d_in[9];
    const float* bh  = (const float*)d_in[10];
    float* out = (float*)d_out;

    int n = in_sizes[0] / 6;   // 50000
    int e = in_sizes[1] / 2;   // 800000

    // node transform + weight precompute + CSR build (parallel scan)
    k_nt     <<<(n * D + 255) / 256, 256>>>(x, Wnt, bnt, n);
    k_makeC  <<<(3 * D * G3 + 255) / 256, 256>>>(wt, Wih);
    k_transW <<<(D * G3 + 255) / 256, 256>>>(Whh);
    k_zero   <<<NBLK, 256>>>();
    k_hist   <<<(e + 255) / 256, 256>>>(ei, e, n);
    k_scanA  <<<NBLK, 256>>>();
    k_scanB  <<<1, 256>>>();
    k_scanC  <<<NBLK, 256>>>(e);
    k_scatter<<<(e + 255) / 256, 256>>>(ei, e, n);

    int aggGrid = (n + 7) / 8;      // one warp per node
    int gruGrid = (n + 31) / 32;    // 32 nodes per block

    // layer 0: g_h -> g_h2
    k_agg<<<aggGrid, 256>>>(0, n);
    k_gru<<<gruGrid, 256>>>(0, 0, nullptr, bi, bh, n);
    // layer 1: g_h2 -> g_h
    k_agg<<<aggGrid, 256>>>(1, n);
    k_gru<<<gruGrid, 256>>>(1, 1, nullptr, bi, bh, n);
    // layer 2: g_h -> d_out
    k_agg<<<aggGrid, 256>>>(0, n);
    k_gru<<<gruGrid, 256>>>(0, 2, out, bi, bh, n);
}